// round 8
// baseline (speedup 1.0000x reference)
#include <cuda_runtime.h>
#include <cuda_fp16.h>
#include <cstdint>

// ============================================================================
// LoRALayer: out[16384,4096] = x[16384,4096] @ W_eff^T + bias
//   W_eff[o,d] = weight[o,d] + sum_r A[d,r]*B[r,o]
// sm_103 (non-'a' PTX): legacy mma.sync fp16 HMMA, fp32 accum, 1 pass.
// R8: R7 + swizzle-XOR factorization for ldmatrix addressing:
//   swz(row*128 + col*16) = row*128 + (col*16 ^ ((row*16)&0x70))
// -> per-thread bases precomputed once; each ldm4 address = (stage+base)^acol16
//    (1 IADD + 1 LOP3). Cuts ~17% alu-pipe overhead + frees regs (was 255).
// ============================================================================

#define DINL __device__ __forceinline__

constexpr int M_DIM = 16384;
constexpr int N_DIM = 4096;
constexpr int K_DIM = 4096;
constexpr int RANK  = 16;

constexpr int BM = 128;
constexpr int BN = 256;
constexpr int BK = 64;
constexpr int NKI = K_DIM / BK;           // 64 k-iterations
constexpr int STAGES = 4;

// per-stage smem (fp16, 128B rows): XH[128][64] WH[256][64]
constexpr int OFF_XH = 0;
constexpr int OFF_WH = 16384;
constexpr int STAGE_B = 49152;
constexpr int SMEM_BYTES = STAGES * STAGE_B;   // 196608

constexpr int SPLIT_BLOCKS = (int)(((size_t)M_DIM * K_DIM) / 8 / 256);  // 32768
constexpr int BUILD_BLOCKS = (K_DIM / 64) * (N_DIM / 256);              // 1024

// ---------------- scratch (device globals; no runtime allocation) ----------
__device__ __half g_xh[(size_t)M_DIM * K_DIM];
__device__ __half g_wh[(size_t)N_DIM * K_DIM];

// ---------------- helpers ---------------------------------------------------
DINL uint32_t smem_u32(const void* p) {
    uint32_t a;
    asm("{ .reg .u64 t; cvta.to.shared.u64 t, %1; cvt.u32.u64 %0, t; }"
        : "=r"(a) : "l"(p));
    return a;
}
// SW128 swizzle for 128-byte rows (Swizzle<3,4,3>)
DINL uint32_t swz(uint32_t x) { return x ^ ((x >> 3) & 0x70); }

DINL void cp16(uint32_t dst, const void* src) {
    asm volatile("cp.async.cg.shared.global [%0], [%1], 16;"
                 :: "r"(dst), "l"(src) : "memory");
}
#define CP_COMMIT() asm volatile("cp.async.commit_group;" ::: "memory")
#define CP_WAIT1()  asm volatile("cp.async.wait_group 1;" ::: "memory")

DINL void ldm4(uint32_t* r, uint32_t addr) {
    asm volatile("ldmatrix.sync.aligned.m8n8.x4.shared.b16 {%0,%1,%2,%3}, [%4];"
                 : "=r"(r[0]), "=r"(r[1]), "=r"(r[2]), "=r"(r[3]) : "r"(addr));
}
DINL void mma16816(float* c, const uint32_t* a, uint32_t b0, uint32_t b1) {
    asm volatile(
        "mma.sync.aligned.m16n8k16.row.col.f32.f16.f16.f32 "
        "{%0,%1,%2,%3}, {%4,%5,%6,%7}, {%8,%9}, {%0,%1,%2,%3};"
        : "+f"(c[0]), "+f"(c[1]), "+f"(c[2]), "+f"(c[3])
        : "r"(a[0]), "r"(a[1]), "r"(a[2]), "r"(a[3]), "r"(b0), "r"(b1));
}

// ============================================================================
// Kernel 1 (fused prep): blocks [0, SPLIT_BLOCKS) convert x -> fp16;
// blocks [SPLIT_BLOCKS, +BUILD_BLOCKS) build W_eff = W + A@B -> fp16.
// ============================================================================
__global__ void __launch_bounds__(256) prep_kernel(
    const float* __restrict__ x,
    const float* __restrict__ weight,   // [N,K] row-major
    const float* __restrict__ A,        // [K,RANK]
    const float* __restrict__ B)        // [RANK,N]
{
    __shared__ float As[64][RANK];
    __shared__ float Bs[RANK][256];

    int tid = threadIdx.x;

    if (blockIdx.x < SPLIT_BLOCKS) {
        size_t e = ((size_t)blockIdx.x * 256 + tid) * 8;
        const float4* p = reinterpret_cast<const float4*>(x + e);
        float4 v0 = p[0], v1 = p[1];
        float vv[8] = {v0.x, v0.y, v0.z, v0.w, v1.x, v1.y, v1.z, v1.w};
        __half h[8];
#pragma unroll
        for (int i = 0; i < 8; i++) h[i] = __float2half_rn(vv[i]);
        *reinterpret_cast<uint4*>(g_xh + e) = *reinterpret_cast<uint4*>(h);
        return;
    }

    int bid2 = blockIdx.x - SPLIT_BLOCKS;
    int kblk = bid2 & 63, nblk = bid2 >> 6;
    int d0 = kblk * 64, o0 = nblk * 256;

    reinterpret_cast<float4*>(&As[0][0])[tid] =
        reinterpret_cast<const float4*>(A + (size_t)d0 * RANK)[tid];
#pragma unroll
    for (int r = 0; r < RANK; r++)
        Bs[r][tid] = B[(size_t)r * N_DIM + o0 + tid];
    __syncthreads();

    int o = o0 + tid;
    const float* wrow = weight + (size_t)o * K_DIM + d0;

#pragma unroll 1
    for (int dc = 0; dc < 64; dc += 8) {
        float4 wa = reinterpret_cast<const float4*>(wrow + dc)[0];
        float4 wb = reinterpret_cast<const float4*>(wrow + dc)[1];
        float w[8] = {wa.x, wa.y, wa.z, wa.w, wb.x, wb.y, wb.z, wb.w};
        __half h[8];
#pragma unroll
        for (int i = 0; i < 8; i++) {
            float s = 0.f;
#pragma unroll
            for (int r = 0; r < RANK; r++) s += As[dc + i][r] * Bs[r][tid];
            h[i] = __float2half_rn(w[i] + s);
        }
        *reinterpret_cast<uint4*>(g_wh + (size_t)o * K_DIM + d0 + dc) =
            *reinterpret_cast<uint4*>(h);
    }
}

// ============================================================================
// Kernel 2: GEMM. CTA = 128x256, 256 thr (8 warps, 64x64 warp tiles),
// BK=64, 4-stage cp.async, fp16 mma -> fp32 accum, 1 pass.
// Fragment double-buffering + XOR-factored ldmatrix addressing.
// ============================================================================
__global__ void __launch_bounds__(256, 1)
gemm_kernel(const float* __restrict__ bias, float* __restrict__ out)
{
    extern __shared__ __align__(1024) char smem[];
    const uint32_t sbase = smem_u32(smem);

    const int tid  = threadIdx.x;
    const int wid  = tid >> 5;
    const int lane = tid & 31;

    // wave-grouped ordering: 16 groups of (8 m) x (16 n) = 128 CTAs/group
    const int bid  = blockIdx.x;
    const int grp  = bid >> 7;
    const int mblk = grp * 8 + ((bid >> 4) & 7);
    const int nblk = bid & 15;

    const int m_base = (wid >> 2) * 64;   // 0 or 64
    const int n_base = (wid & 3) * 64;    // 0,64,128,192

    // ldmatrix lane-relative mapping
    const int r16   = (lane & 7) + ((lane >> 3) & 1) * 8;
    const uint32_t cx = (uint32_t)(lane >> 4) << 4;   // chalf*16 (bit 4)

    // per-thread swizzle bases: addr = (stage_base + base) ^ (acol*16)
    uint32_t base_x[4], base_w[4];
#pragma unroll
    for (int mt = 0; mt < 4; mt++) {
        uint32_t row = (uint32_t)(m_base + mt * 16 + r16);
        base_x[mt] = OFF_XH + row * 128 + ((row << 4) & 0x70);
    }
#pragma unroll
    for (int t = 0; t < 4; t++) {
        uint32_t row = (uint32_t)(n_base + t * 16 + r16);
        base_w[t] = OFF_WH + row * 128 + ((row << 4) & 0x70);
    }

    // ---------------- stage loader (256 threads) ----------------
    auto load_stage = [&](int buf, int kblk) {
        if (kblk < NKI) {
            uint32_t sb = sbase + buf * STAGE_B;
            int k0 = kblk * BK;
#pragma unroll
            for (int i = 0; i < 4; i++) {           // X: 1024 16B chunks
                int q = tid + i * 256;
                int m = q >> 3, c = q & 7;
                uint32_t so = swz((uint32_t)(m * 128 + c * 16));
                size_t g = (size_t)(mblk * BM + m) * K_DIM + k0 + c * 8;
                cp16(sb + OFF_XH + so, g_xh + g);
            }
#pragma unroll
            for (int i = 0; i < 8; i++) {           // W: 2048 16B chunks
                int q = tid + i * 256;
                int n = q >> 3, c = q & 7;
                uint32_t so = swz((uint32_t)(n * 128 + c * 16));
                size_t g = (size_t)(nblk * BN + n) * K_DIM + k0 + c * 8;
                cp16(sb + OFF_WH + so, g_wh + g);
            }
        }
        CP_COMMIT();
    };

    float acc[4][8][4];
#pragma unroll
    for (int mt = 0; mt < 4; mt++)
#pragma unroll
        for (int nt = 0; nt < 8; nt++)
#pragma unroll
            for (int q = 0; q < 4; q++) acc[mt][nt][q] = 0.f;

    load_stage(0, 0);
    load_stage(1, 1);
    load_stage(2, 2);
    CP_WAIT1();                 // completes stages 0 and 1
    __syncthreads();

    uint32_t xa[2][4][4], wf[2][4][4];
#pragma unroll
    for (int mt = 0; mt < 4; mt++) ldm4(xa[0][mt], (sbase + base_x[mt]) ^ cx);
#pragma unroll
    for (int t = 0; t < 4; t++)  ldm4(wf[0][t],  (sbase + base_w[t]) ^ cx);

#pragma unroll 1
    for (int it = 0; it < NKI; it++) {
        uint32_t sb  = sbase + (it & 3) * STAGE_B;
        uint32_t sbn = sbase + ((it + 1) & 3) * STAGE_B;

#pragma unroll
        for (int kc = 0; kc < 4; kc++) {
            const int cur = kc & 1, nxt = cur ^ 1;
            // prefetch source: next kc in this stage, or kc0 of next stage
            const uint32_t psb  = (kc < 3) ? sb : sbn;
            const uint32_t pxor = (kc < 3) ? ((uint32_t)((kc + 1) << 5) | cx) : cx;

            // 16 MMAs (mt 0..1)
#pragma unroll
            for (int mt = 0; mt < 2; mt++)
#pragma unroll
                for (int nt = 0; nt < 8; nt++)
                    mma16816(acc[mt][nt], xa[cur][mt],
                             wf[cur][nt >> 1][nt & 1], wf[cur][nt >> 1][(nt & 1) + 2]);

            // prefetch next X frags under the MMA stream
#pragma unroll
            for (int mt = 0; mt < 4; mt++)
                ldm4(xa[nxt][mt], (psb + base_x[mt]) ^ pxor);

            // 16 MMAs (mt 2..3)
#pragma unroll
            for (int mt = 2; mt < 4; mt++)
#pragma unroll
                for (int nt = 0; nt < 8; nt++)
                    mma16816(acc[mt][nt], xa[cur][mt],
                             wf[cur][nt >> 1][nt & 1], wf[cur][nt >> 1][(nt & 1) + 2]);

            // prefetch next W frags
#pragma unroll
            for (int t = 0; t < 4; t++)
                ldm4(wf[nxt][t], (psb + base_w[t]) ^ pxor);
        }

        // issue next stage load; keep <=1 group outstanding so stage it+2
        // is complete (and visible after the barrier) entering iter it+1.
        load_stage((it + 3) & 3, it + 3);
        CP_WAIT1();
        __syncthreads();
    }

    // ---------------- epilogue: bias add + fp32 store ----------------
    const int gm = mblk * BM + m_base;
    const int gn = nblk * BN + n_base;
#pragma unroll
    for (int nt = 0; nt < 8; nt++) {
        int col = gn + nt * 8 + 2 * (lane & 3);
        float2 bv = *reinterpret_cast<const float2*>(bias + col);
#pragma unroll
        for (int mt = 0; mt < 4; mt++) {
            int row0 = gm + mt * 16 + (lane >> 2);
            float2 v0 = {acc[mt][nt][0] + bv.x, acc[mt][nt][1] + bv.y};
            float2 v1 = {acc[mt][nt][2] + bv.x, acc[mt][nt][3] + bv.y};
            *reinterpret_cast<float2*>(out + (size_t)row0 * N_DIM + col) = v0;
            *reinterpret_cast<float2*>(out + (size_t)(row0 + 8) * N_DIM + col) = v1;
        }
    }
}

// ============================================================================
// Launch
// ============================================================================
extern "C" void kernel_launch(void* const* d_in, const int* in_sizes, int n_in,
                              void* d_out, int out_size)
{
    const float* x      = (const float*)d_in[0];
    const float* A      = (const float*)d_in[1];
    const float* B      = (const float*)d_in[2];
    const float* weight = (const float*)d_in[3];
    const float* bias   = (const float*)d_in[4];
    float* out = (float*)d_out;

    cudaFuncSetAttribute(gemm_kernel,
                         cudaFuncAttributeMaxDynamicSharedMemorySize, SMEM_BYTES);

    prep_kernel<<<SPLIT_BLOCKS + BUILD_BLOCKS, 256>>>(x, weight, A, B);
    gemm_kernel<<<(M_DIM / BM) * (N_DIM / BN), 256, SMEM_BYTES>>>(bias, out);
}

// round 9
// speedup vs baseline: 1.0135x; 1.0135x over previous
#include <cuda_runtime.h>
#include <cuda_fp16.h>
#include <cstdint>

// ============================================================================
// LoRALayer: out[16384,4096] = x[16384,4096] @ W_eff^T + bias
//   W_eff[o,d] = weight[o,d] + sum_r A[d,r]*B[r,o]
// sm_103 (non-'a' PTX): legacy mma.sync fp16 HMMA, fp32 accum, 1 pass.
// R9: strength-reduced stage loader. Global srcs = 1 running pointer per
// array + constant imm offsets (chunk stride 32 rows = 32*4096 elems is
// compile-time); smem dsts = precomputed swizzled base + i*4096 (the XOR
// term is invariant in i because 32i preserves row&7). Kills the ~31%
// fma+alu pipe load measured in R8's loader.
// ============================================================================

#define DINL __device__ __forceinline__

constexpr int M_DIM = 16384;
constexpr int N_DIM = 4096;
constexpr int K_DIM = 4096;
constexpr int RANK  = 16;

constexpr int BM = 128;
constexpr int BN = 256;
constexpr int BK = 64;
constexpr int NKI = K_DIM / BK;           // 64 k-iterations
constexpr int STAGES = 4;

// per-stage smem (fp16, 128B rows): XH[128][64] WH[256][64]
constexpr int OFF_XH = 0;
constexpr int OFF_WH = 16384;
constexpr int STAGE_B = 49152;
constexpr int SMEM_BYTES = STAGES * STAGE_B;   // 196608

constexpr int SPLIT_BLOCKS = (int)(((size_t)M_DIM * K_DIM) / 8 / 256);  // 32768
constexpr int BUILD_BLOCKS = (K_DIM / 64) * (N_DIM / 256);              // 1024

// ---------------- scratch (device globals; no runtime allocation) ----------
__device__ __half g_xh[(size_t)M_DIM * K_DIM];
__device__ __half g_wh[(size_t)N_DIM * K_DIM];

// ---------------- helpers ---------------------------------------------------
DINL uint32_t smem_u32(const void* p) {
    uint32_t a;
    asm("{ .reg .u64 t; cvta.to.shared.u64 t, %1; cvt.u32.u64 %0, t; }"
        : "=r"(a) : "l"(p));
    return a;
}
// SW128 swizzle for 128-byte rows (Swizzle<3,4,3>)
DINL uint32_t swz(uint32_t x) { return x ^ ((x >> 3) & 0x70); }

DINL void cp16(uint32_t dst, const void* src) {
    asm volatile("cp.async.cg.shared.global [%0], [%1], 16;"
                 :: "r"(dst), "l"(src) : "memory");
}
#define CP_COMMIT() asm volatile("cp.async.commit_group;" ::: "memory")
#define CP_WAIT1()  asm volatile("cp.async.wait_group 1;" ::: "memory")

DINL void ldm4(uint32_t* r, uint32_t addr) {
    asm volatile("ldmatrix.sync.aligned.m8n8.x4.shared.b16 {%0,%1,%2,%3}, [%4];"
                 : "=r"(r[0]), "=r"(r[1]), "=r"(r[2]), "=r"(r[3]) : "r"(addr));
}
DINL void mma16816(float* c, const uint32_t* a, uint32_t b0, uint32_t b1) {
    asm volatile(
        "mma.sync.aligned.m16n8k16.row.col.f32.f16.f16.f32 "
        "{%0,%1,%2,%3}, {%4,%5,%6,%7}, {%8,%9}, {%0,%1,%2,%3};"
        : "+f"(c[0]), "+f"(c[1]), "+f"(c[2]), "+f"(c[3])
        : "r"(a[0]), "r"(a[1]), "r"(a[2]), "r"(a[3]), "r"(b0), "r"(b1));
}

// ============================================================================
// Kernel 1 (fused prep): blocks [0, SPLIT_BLOCKS) convert x -> fp16;
// blocks [SPLIT_BLOCKS, +BUILD_BLOCKS) build W_eff = W + A@B -> fp16.
// ============================================================================
__global__ void __launch_bounds__(256) prep_kernel(
    const float* __restrict__ x,
    const float* __restrict__ weight,   // [N,K] row-major
    const float* __restrict__ A,        // [K,RANK]
    const float* __restrict__ B)        // [RANK,N]
{
    __shared__ float As[64][RANK];
    __shared__ float Bs[RANK][256];

    int tid = threadIdx.x;

    if (blockIdx.x < SPLIT_BLOCKS) {
        size_t e = ((size_t)blockIdx.x * 256 + tid) * 8;
        const float4* p = reinterpret_cast<const float4*>(x + e);
        float4 v0 = p[0], v1 = p[1];
        float vv[8] = {v0.x, v0.y, v0.z, v0.w, v1.x, v1.y, v1.z, v1.w};
        __half h[8];
#pragma unroll
        for (int i = 0; i < 8; i++) h[i] = __float2half_rn(vv[i]);
        *reinterpret_cast<uint4*>(g_xh + e) = *reinterpret_cast<uint4*>(h);
        return;
    }

    int bid2 = blockIdx.x - SPLIT_BLOCKS;
    int kblk = bid2 & 63, nblk = bid2 >> 6;
    int d0 = kblk * 64, o0 = nblk * 256;

    reinterpret_cast<float4*>(&As[0][0])[tid] =
        reinterpret_cast<const float4*>(A + (size_t)d0 * RANK)[tid];
#pragma unroll
    for (int r = 0; r < RANK; r++)
        Bs[r][tid] = B[(size_t)r * N_DIM + o0 + tid];
    __syncthreads();

    int o = o0 + tid;
    const float* wrow = weight + (size_t)o * K_DIM + d0;

#pragma unroll 1
    for (int dc = 0; dc < 64; dc += 8) {
        float4 wa = reinterpret_cast<const float4*>(wrow + dc)[0];
        float4 wb = reinterpret_cast<const float4*>(wrow + dc)[1];
        float w[8] = {wa.x, wa.y, wa.z, wa.w, wb.x, wb.y, wb.z, wb.w};
        __half h[8];
#pragma unroll
        for (int i = 0; i < 8; i++) {
            float s = 0.f;
#pragma unroll
            for (int r = 0; r < RANK; r++) s += As[dc + i][r] * Bs[r][tid];
            h[i] = __float2half_rn(w[i] + s);
        }
        *reinterpret_cast<uint4*>(g_wh + (size_t)o * K_DIM + d0 + dc) =
            *reinterpret_cast<uint4*>(h);
    }
}

// ============================================================================
// Kernel 2: GEMM. CTA = 128x256, 256 thr (8 warps, 64x64 warp tiles),
// BK=64, 4-stage cp.async, fp16 mma -> fp32 accum, 1 pass.
// Strength-reduced loader + frag double-buffering + XOR-factored ldmatrix.
// ============================================================================
__global__ void __launch_bounds__(256, 1)
gemm_kernel(const float* __restrict__ bias, float* __restrict__ out)
{
    extern __shared__ __align__(1024) char smem[];
    const uint32_t sbase = smem_u32(smem);

    const int tid  = threadIdx.x;
    const int wid  = tid >> 5;
    const int lane = tid & 31;

    // wave-grouped ordering: 16 groups of (8 m) x (16 n) = 128 CTAs/group
    const int bid  = blockIdx.x;
    const int grp  = bid >> 7;
    const int mblk = grp * 8 + ((bid >> 4) & 7);
    const int nblk = bid & 15;

    const int m_base = (wid >> 2) * 64;   // 0 or 64
    const int n_base = (wid & 3) * 64;    // 0,64,128,192

    // ldmatrix lane-relative mapping
    const int r16   = (lane & 7) + ((lane >> 3) & 1) * 8;
    const uint32_t cx = (uint32_t)(lane >> 4) << 4;   // chalf*16 (bit 4)

    // per-thread swizzle bases for ldmatrix: addr = (stage+base) ^ (acol*16)
    uint32_t base_x[4], base_w[4];
#pragma unroll
    for (int mt = 0; mt < 4; mt++) {
        uint32_t row = (uint32_t)(m_base + mt * 16 + r16);
        base_x[mt] = OFF_XH + row * 128 + ((row << 4) & 0x70);
    }
#pragma unroll
    for (int t = 0; t < 4; t++) {
        uint32_t row = (uint32_t)(n_base + t * 16 + r16);
        base_w[t] = OFF_WH + row * 128 + ((row << 4) & 0x70);
    }

    // ---------------- strength-reduced loader state ----------------
    // chunk i covers row (tid>>3)+32i, col (tid&7)*8; row stride 32*K_DIM elems
    const int lrow = tid >> 3;            // 0..31
    const int lcol = (tid & 7) * 8;       // 0..56
    const __half* px = g_xh + (size_t)(mblk * BM + lrow) * K_DIM + lcol;
    const __half* pw = g_wh + (size_t)(nblk * BN + lrow) * K_DIM + lcol;
    // swizzled smem dst bases (XOR term invariant across i: 32i keeps row&7)
    const uint32_t sox = OFF_XH + swz((uint32_t)(lrow * 128 + (tid & 7) * 16));
    const uint32_t sow = OFF_WH + swz((uint32_t)(lrow * 128 + (tid & 7) * 16));

    auto load_stage = [&](int buf, const __half* pxk, const __half* pwk,
                          bool valid) {
        if (valid) {
            uint32_t db = sbase + buf * STAGE_B;
#pragma unroll
            for (int i = 0; i < 4; i++)
                cp16(db + sox + i * 4096, pxk + (size_t)i * 32 * K_DIM);
#pragma unroll
            for (int i = 0; i < 8; i++)
                cp16(db + sow + i * 4096, pwk + (size_t)i * 32 * K_DIM);
        }
        CP_COMMIT();
    };

    float acc[4][8][4];
#pragma unroll
    for (int mt = 0; mt < 4; mt++)
#pragma unroll
        for (int nt = 0; nt < 8; nt++)
#pragma unroll
            for (int q = 0; q < 4; q++) acc[mt][nt][q] = 0.f;

    load_stage(0, px,           pw,           true);
    load_stage(1, px + BK,      pw + BK,      true);
    load_stage(2, px + 2 * BK,  pw + 2 * BK,  true);
    px += 3 * BK;  pw += 3 * BK;            // next stage to load = kblk 3
    CP_WAIT1();                 // completes stages 0 and 1
    __syncthreads();

    uint32_t xa[2][4][4], wf[2][4][4];
#pragma unroll
    for (int mt = 0; mt < 4; mt++) ldm4(xa[0][mt], (sbase + base_x[mt]) ^ cx);
#pragma unroll
    for (int t = 0; t < 4; t++)  ldm4(wf[0][t],  (sbase + base_w[t]) ^ cx);

#pragma unroll 1
    for (int it = 0; it < NKI; it++) {
        uint32_t sb  = sbase + (it & 3) * STAGE_B;
        uint32_t sbn = sbase + ((it + 1) & 3) * STAGE_B;

#pragma unroll
        for (int kc = 0; kc < 4; kc++) {
            const int cur = kc & 1, nxt = cur ^ 1;
            // prefetch source: next kc in this stage, or kc0 of next stage
            const uint32_t psb  = (kc < 3) ? sb : sbn;
            const uint32_t pxor = (kc < 3) ? ((uint32_t)((kc + 1) << 5) | cx) : cx;

            // 16 MMAs (mt 0..1)
#pragma unroll
            for (int mt = 0; mt < 2; mt++)
#pragma unroll
                for (int nt = 0; nt < 8; nt++)
                    mma16816(acc[mt][nt], xa[cur][mt],
                             wf[cur][nt >> 1][nt & 1], wf[cur][nt >> 1][(nt & 1) + 2]);

            // prefetch next X frags under the MMA stream
#pragma unroll
            for (int mt = 0; mt < 4; mt++)
                ldm4(xa[nxt][mt], (psb + base_x[mt]) ^ pxor);

            // 16 MMAs (mt 2..3)
#pragma unroll
            for (int mt = 2; mt < 4; mt++)
#pragma unroll
                for (int nt = 0; nt < 8; nt++)
                    mma16816(acc[mt][nt], xa[cur][mt],
                             wf[cur][nt >> 1][nt & 1], wf[cur][nt >> 1][(nt & 1) + 2]);

            // prefetch next W frags
#pragma unroll
            for (int t = 0; t < 4; t++)
                ldm4(wf[nxt][t], (psb + base_w[t]) ^ pxor);
        }

        // issue next stage load; keep <=1 group outstanding so stage it+2
        // is complete (and visible after the barrier) entering iter it+1.
        load_stage((it + 3) & 3, px, pw, it + 3 < NKI);
        px += BK;  pw += BK;
        CP_WAIT1();
        __syncthreads();
    }

    // ---------------- epilogue: bias add + fp32 store ----------------
    const int gm = mblk * BM + m_base;
    const int gn = nblk * BN + n_base;
#pragma unroll
    for (int nt = 0; nt < 8; nt++) {
        int col = gn + nt * 8 + 2 * (lane & 3);
        float2 bv = *reinterpret_cast<const float2*>(bias + col);
#pragma unroll
        for (int mt = 0; mt < 4; mt++) {
            int row0 = gm + mt * 16 + (lane >> 2);
            float2 v0 = {acc[mt][nt][0] + bv.x, acc[mt][nt][1] + bv.y};
            float2 v1 = {acc[mt][nt][2] + bv.x, acc[mt][nt][3] + bv.y};
            *reinterpret_cast<float2*>(out + (size_t)row0 * N_DIM + col) = v0;
            *reinterpret_cast<float2*>(out + (size_t)(row0 + 8) * N_DIM + col) = v1;
        }
    }
}

// ============================================================================
// Launch
// ============================================================================
extern "C" void kernel_launch(void* const* d_in, const int* in_sizes, int n_in,
                              void* d_out, int out_size)
{
    const float* x      = (const float*)d_in[0];
    const float* A      = (const float*)d_in[1];
    const float* B      = (const float*)d_in[2];
    const float* weight = (const float*)d_in[3];
    const float* bias   = (const float*)d_in[4];
    float* out = (float*)d_out;

    cudaFuncSetAttribute(gemm_kernel,
                         cudaFuncAttributeMaxDynamicSharedMemorySize, SMEM_BYTES);

    prep_kernel<<<SPLIT_BLOCKS + BUILD_BLOCKS, 256>>>(x, weight, A, B);
    gemm_kernel<<<(M_DIM / BM) * (N_DIM / BN), 256, SMEM_BYTES>>>(bias, out);
}

// round 10
// speedup vs baseline: 1.1098x; 1.0950x over previous
#include <cuda_runtime.h>
#include <cuda_fp16.h>
#include <cstdint>

// ============================================================================
// LoRALayer: out[16384,4096] = x[16384,4096] @ W_eff^T + bias
//   W_eff[o,d] = weight[o,d] + sum_r A[d,r]*B[r,o]
// sm_103 (non-'a' PTX): legacy mma.sync fp16 HMMA, fp32 accum, 1 pass.
// R10: 2 independent CTAs per SM (128 threads each, 4 warps of 64x64,
// CTA tile 128x128, 3 stages x 32KB). Decouples barrier stalls: while one
// CTA waits at wait_group/syncthreads, the other CTA's warps feed the
// tensor pipe (measured 26% tensor-idle with 1 CTA/SM in R7-R9).
// ============================================================================

#define DINL __device__ __forceinline__

constexpr int M_DIM = 16384;
constexpr int N_DIM = 4096;
constexpr int K_DIM = 4096;
constexpr int RANK  = 16;

constexpr int BM = 128;
constexpr int BN = 128;
constexpr int BK = 64;
constexpr int NKI = K_DIM / BK;           // 64 k-iterations
constexpr int STAGES = 3;

// per-stage smem (fp16, 128B rows): XH[128][64] WH[128][64]
constexpr int OFF_XH = 0;
constexpr int OFF_WH = 16384;
constexpr int STAGE_B = 32768;
constexpr int SMEM_BYTES = STAGES * STAGE_B;   // 98304 (<=113.5KB for occ 2)

constexpr int SPLIT_BLOCKS = (int)(((size_t)M_DIM * K_DIM) / 8 / 256);  // 32768
constexpr int BUILD_BLOCKS = (K_DIM / 64) * (N_DIM / 256);              // 1024

// ---------------- scratch (device globals; no runtime allocation) ----------
__device__ __half g_xh[(size_t)M_DIM * K_DIM];
__device__ __half g_wh[(size_t)N_DIM * K_DIM];

// ---------------- helpers ---------------------------------------------------
DINL uint32_t smem_u32(const void* p) {
    uint32_t a;
    asm("{ .reg .u64 t; cvta.to.shared.u64 t, %1; cvt.u32.u64 %0, t; }"
        : "=r"(a) : "l"(p));
    return a;
}
// SW128 swizzle for 128-byte rows (Swizzle<3,4,3>)
DINL uint32_t swz(uint32_t x) { return x ^ ((x >> 3) & 0x70); }

DINL void cp16(uint32_t dst, const void* src) {
    asm volatile("cp.async.cg.shared.global [%0], [%1], 16;"
                 :: "r"(dst), "l"(src) : "memory");
}
#define CP_COMMIT() asm volatile("cp.async.commit_group;" ::: "memory")
#define CP_WAIT0()  asm volatile("cp.async.wait_group 0;" ::: "memory")

DINL void ldm4(uint32_t* r, uint32_t addr) {
    asm volatile("ldmatrix.sync.aligned.m8n8.x4.shared.b16 {%0,%1,%2,%3}, [%4];"
                 : "=r"(r[0]), "=r"(r[1]), "=r"(r[2]), "=r"(r[3]) : "r"(addr));
}
DINL void mma16816(float* c, const uint32_t* a, uint32_t b0, uint32_t b1) {
    asm volatile(
        "mma.sync.aligned.m16n8k16.row.col.f32.f16.f16.f32 "
        "{%0,%1,%2,%3}, {%4,%5,%6,%7}, {%8,%9}, {%0,%1,%2,%3};"
        : "+f"(c[0]), "+f"(c[1]), "+f"(c[2]), "+f"(c[3])
        : "r"(a[0]), "r"(a[1]), "r"(a[2]), "r"(a[3]), "r"(b0), "r"(b1));
}

// ============================================================================
// Kernel 1 (fused prep): blocks [0, SPLIT_BLOCKS) convert x -> fp16;
// blocks [SPLIT_BLOCKS, +BUILD_BLOCKS) build W_eff = W + A@B -> fp16.
// ============================================================================
__global__ void __launch_bounds__(256) prep_kernel(
    const float* __restrict__ x,
    const float* __restrict__ weight,   // [N,K] row-major
    const float* __restrict__ A,        // [K,RANK]
    const float* __restrict__ B)        // [RANK,N]
{
    __shared__ float As[64][RANK];
    __shared__ float Bs[RANK][256];

    int tid = threadIdx.x;

    if (blockIdx.x < SPLIT_BLOCKS) {
        size_t e = ((size_t)blockIdx.x * 256 + tid) * 8;
        const float4* p = reinterpret_cast<const float4*>(x + e);
        float4 v0 = p[0], v1 = p[1];
        float vv[8] = {v0.x, v0.y, v0.z, v0.w, v1.x, v1.y, v1.z, v1.w};
        __half h[8];
#pragma unroll
        for (int i = 0; i < 8; i++) h[i] = __float2half_rn(vv[i]);
        *reinterpret_cast<uint4*>(g_xh + e) = *reinterpret_cast<uint4*>(h);
        return;
    }

    int bid2 = blockIdx.x - SPLIT_BLOCKS;
    int kblk = bid2 & 63, nblk = bid2 >> 6;
    int d0 = kblk * 64, o0 = nblk * 256;

    reinterpret_cast<float4*>(&As[0][0])[tid] =
        reinterpret_cast<const float4*>(A + (size_t)d0 * RANK)[tid];
#pragma unroll
    for (int r = 0; r < RANK; r++)
        Bs[r][tid] = B[(size_t)r * N_DIM + o0 + tid];
    __syncthreads();

    int o = o0 + tid;
    const float* wrow = weight + (size_t)o * K_DIM + d0;

#pragma unroll 1
    for (int dc = 0; dc < 64; dc += 8) {
        float4 wa = reinterpret_cast<const float4*>(wrow + dc)[0];
        float4 wb = reinterpret_cast<const float4*>(wrow + dc)[1];
        float w[8] = {wa.x, wa.y, wa.z, wa.w, wb.x, wb.y, wb.z, wb.w};
        __half h[8];
#pragma unroll
        for (int i = 0; i < 8; i++) {
            float s = 0.f;
#pragma unroll
            for (int r = 0; r < RANK; r++) s += As[dc + i][r] * Bs[r][tid];
            h[i] = __float2half_rn(w[i] + s);
        }
        *reinterpret_cast<uint4*>(g_wh + (size_t)o * K_DIM + d0 + dc) =
            *reinterpret_cast<uint4*>(h);
    }
}

// ============================================================================
// Kernel 2: GEMM. CTA = 128x128, 128 thr (4 warps, 64x64 tiles), 2 CTAs/SM,
// BK=64, 3-stage cp.async (load issued at iter start, wait0 at iter end),
// fp16 mma -> fp32 accum, frag double-buffering, XOR-factored ldmatrix.
// ============================================================================
__global__ void __launch_bounds__(128, 2)
gemm_kernel(const float* __restrict__ bias, float* __restrict__ out)
{
    extern __shared__ __align__(1024) char smem[];
    const uint32_t sbase = smem_u32(smem);

    const int tid  = threadIdx.x;
    const int wid  = tid >> 5;
    const int lane = tid & 31;

    // grouped ordering: groups of (8 m) x (32 n) = 256 CTAs
    const int bid  = blockIdx.x;
    const int grp  = bid >> 8;
    const int mblk = grp * 8 + ((bid >> 5) & 7);
    const int nblk = bid & 31;

    const int m_base = (wid >> 1) * 64;   // 0 or 64
    const int n_base = (wid & 1) * 64;    // 0 or 64

    // ldmatrix lane-relative mapping
    const int r16   = (lane & 7) + ((lane >> 3) & 1) * 8;
    const uint32_t cx = (uint32_t)(lane >> 4) << 4;   // chalf*16 (bit 4)

    // per-thread swizzle bases for ldmatrix: addr = (stage+base) ^ (acol*16)
    uint32_t base_x[4], base_w[4];
#pragma unroll
    for (int mt = 0; mt < 4; mt++) {
        uint32_t row = (uint32_t)(m_base + mt * 16 + r16);
        base_x[mt] = OFF_XH + row * 128 + ((row << 4) & 0x70);
    }
#pragma unroll
    for (int t = 0; t < 4; t++) {
        uint32_t row = (uint32_t)(n_base + t * 16 + r16);
        base_w[t] = OFF_WH + row * 128 + ((row << 4) & 0x70);
    }

    // ---------------- strength-reduced loader state (128 threads) ----------
    // chunk i covers row (tid>>3)+16i, col (tid&7)*8; 16 rows preserves row&7
    const int lrow = tid >> 3;            // 0..15
    const int lcol = (tid & 7) * 8;
    const __half* px = g_xh + (size_t)(mblk * BM + lrow) * K_DIM + lcol;
    const __half* pw = g_wh + (size_t)(nblk * BN + lrow) * K_DIM + lcol;
    const uint32_t sox = OFF_XH + swz((uint32_t)(lrow * 128 + (tid & 7) * 16));
    const uint32_t sow = OFF_WH + swz((uint32_t)(lrow * 128 + (tid & 7) * 16));

    auto load_stage = [&](uint32_t db, const __half* pxk, const __half* pwk,
                          bool valid) {
        if (valid) {
#pragma unroll
            for (int i = 0; i < 8; i++)
                cp16(db + sox + i * 2048, pxk + (size_t)i * 16 * K_DIM);
#pragma unroll
            for (int i = 0; i < 8; i++)
                cp16(db + sow + i * 2048, pwk + (size_t)i * 16 * K_DIM);
        }
        CP_COMMIT();
    };

    float acc[4][8][4];
#pragma unroll
    for (int mt = 0; mt < 4; mt++)
#pragma unroll
        for (int nt = 0; nt < 8; nt++)
#pragma unroll
            for (int q = 0; q < 4; q++) acc[mt][nt][q] = 0.f;

    // prologue: stages 0 and 1 fully loaded
    load_stage(sbase,           px,      pw,      true);
    load_stage(sbase + STAGE_B, px + BK, pw + BK, true);
    px += 2 * BK;  pw += 2 * BK;
    CP_WAIT0();
    __syncthreads();

    uint32_t xa[2][4][4], wf[2][4][4];
#pragma unroll
    for (int mt = 0; mt < 4; mt++) ldm4(xa[0][mt], (sbase + base_x[mt]) ^ cx);
#pragma unroll
    for (int t = 0; t < 4; t++)  ldm4(wf[0][t],  (sbase + base_w[t]) ^ cx);

    int s_cur = 0, s_nxt = 1, s_ld = 2;   // stage indices (mod 3)

#pragma unroll 1
    for (int it = 0; it < NKI; it++) {
        // issue next-next stage load at iter start; it has a whole iteration
        // of MMAs (~2000 cyc >> mem latency) to complete before wait0 below.
        load_stage(sbase + s_ld * STAGE_B, px, pw, it + 2 < NKI);
        px += BK;  pw += BK;

        const uint32_t sb  = sbase + s_cur * STAGE_B;
        const uint32_t sbn = sbase + s_nxt * STAGE_B;

#pragma unroll
        for (int kc = 0; kc < 4; kc++) {
            const int cur = kc & 1, nxt = cur ^ 1;
            // prefetch source: next kc in this stage, or kc0 of next stage
            const uint32_t psb  = (kc < 3) ? sb : sbn;
            const uint32_t pxor = (kc < 3) ? ((uint32_t)((kc + 1) << 5) | cx) : cx;

            // 16 MMAs (mt 0..1)
#pragma unroll
            for (int mt = 0; mt < 2; mt++)
#pragma unroll
                for (int nt = 0; nt < 8; nt++)
                    mma16816(acc[mt][nt], xa[cur][mt],
                             wf[cur][nt >> 1][nt & 1], wf[cur][nt >> 1][(nt & 1) + 2]);

            // prefetch next X frags under the MMA stream
#pragma unroll
            for (int mt = 0; mt < 4; mt++)
                ldm4(xa[nxt][mt], (psb + base_x[mt]) ^ pxor);

            // 16 MMAs (mt 2..3)
#pragma unroll
            for (int mt = 2; mt < 4; mt++)
#pragma unroll
                for (int nt = 0; nt < 8; nt++)
                    mma16816(acc[mt][nt], xa[cur][mt],
                             wf[cur][nt >> 1][nt & 1], wf[cur][nt >> 1][(nt & 1) + 2]);

            // prefetch next W frags
#pragma unroll
            for (int t = 0; t < 4; t++)
                ldm4(wf[nxt][t], (psb + base_w[t]) ^ pxor);
        }

        // stage it+1 was completed by the wait at end of iter it-1 (its load
        // was issued at start of iter it-1); here wait for the load issued
        // at the start of THIS iter (stage it+2) -> ready for next iter's
        // cross-boundary prefetch. Then barrier before overwriting s_cur.
        CP_WAIT0();
        __syncthreads();

        int t0 = s_cur; s_cur = s_nxt; s_nxt = s_ld; s_ld = t0;
    }

    // ---------------- epilogue: bias add + fp32 store ----------------
    const int gm = mblk * BM + m_base;
    const int gn = nblk * BN + n_base;
#pragma unroll
    for (int nt = 0; nt < 8; nt++) {
        int col = gn + nt * 8 + 2 * (lane & 3);
        float2 bv = *reinterpret_cast<const float2*>(bias + col);
#pragma unroll
        for (int mt = 0; mt < 4; mt++) {
            int row0 = gm + mt * 16 + (lane >> 2);
            float2 v0 = {acc[mt][nt][0] + bv.x, acc[mt][nt][1] + bv.y};
            float2 v1 = {acc[mt][nt][2] + bv.x, acc[mt][nt][3] + bv.y};
            *reinterpret_cast<float2*>(out + (size_t)row0 * N_DIM + col) = v0;
            *reinterpret_cast<float2*>(out + (size_t)(row0 + 8) * N_DIM + col) = v1;
        }
    }
}

// ============================================================================
// Launch
// ============================================================================
extern "C" void kernel_launch(void* const* d_in, const int* in_sizes, int n_in,
                              void* d_out, int out_size)
{
    const float* x      = (const float*)d_in[0];
    const float* A      = (const float*)d_in[1];
    const float* B      = (const float*)d_in[2];
    const float* weight = (const float*)d_in[3];
    const float* bias   = (const float*)d_in[4];
    float* out = (float*)d_out;

    cudaFuncSetAttribute(gemm_kernel,
                         cudaFuncAttributeMaxDynamicSharedMemorySize, SMEM_BYTES);

    prep_kernel<<<SPLIT_BLOCKS + BUILD_BLOCKS, 256>>>(x, weight, A, B);
    gemm_kernel<<<(M_DIM / BM) * (N_DIM / BN), 128, SMEM_BYTES>>>(bias, out);
}

// round 11
// speedup vs baseline: 1.1257x; 1.0144x over previous
#include <cuda_runtime.h>
#include <cuda_fp16.h>
#include <cstdint>

// ============================================================================
// LoRALayer: out[16384,4096] = x[16384,4096] @ W_eff^T + bias
//   W_eff[o,d] = weight[o,d] + sum_r A[d,r]*B[r,o]
// sm_103 (non-'a' PTX): legacy mma.sync fp16 HMMA, fp32 accum, 1 pass.
// R11: R10 (2 CTAs/SM, 128x128, 3 stages) + fine-grained LDSM/MMA
// interleave: each kc = 4 groups of [8 MMA][2 ldm4], giving every prefetch
// >=8 MMAs of use-distance and spreading smem wavefronts evenly.
// ============================================================================

#define DINL __device__ __forceinline__

constexpr int M_DIM = 16384;
constexpr int N_DIM = 4096;
constexpr int K_DIM = 4096;
constexpr int RANK  = 16;

constexpr int BM = 128;
constexpr int BN = 128;
constexpr int BK = 64;
constexpr int NKI = K_DIM / BK;           // 64 k-iterations
constexpr int STAGES = 3;

// per-stage smem (fp16, 128B rows): XH[128][64] WH[128][64]
constexpr int OFF_XH = 0;
constexpr int OFF_WH = 16384;
constexpr int STAGE_B = 32768;
constexpr int SMEM_BYTES = STAGES * STAGE_B;   // 98304 (<=113.5KB for occ 2)

constexpr int SPLIT_BLOCKS = (int)(((size_t)M_DIM * K_DIM) / 8 / 256);  // 32768
constexpr int BUILD_BLOCKS = (K_DIM / 64) * (N_DIM / 256);              // 1024

// ---------------- scratch (device globals; no runtime allocation) ----------
__device__ __half g_xh[(size_t)M_DIM * K_DIM];
__device__ __half g_wh[(size_t)N_DIM * K_DIM];

// ---------------- helpers ---------------------------------------------------
DINL uint32_t smem_u32(const void* p) {
    uint32_t a;
    asm("{ .reg .u64 t; cvta.to.shared.u64 t, %1; cvt.u32.u64 %0, t; }"
        : "=r"(a) : "l"(p));
    return a;
}
// SW128 swizzle for 128-byte rows (Swizzle<3,4,3>)
DINL uint32_t swz(uint32_t x) { return x ^ ((x >> 3) & 0x70); }

DINL void cp16(uint32_t dst, const void* src) {
    asm volatile("cp.async.cg.shared.global [%0], [%1], 16;"
                 :: "r"(dst), "l"(src) : "memory");
}
#define CP_COMMIT() asm volatile("cp.async.commit_group;" ::: "memory")
#define CP_WAIT0()  asm volatile("cp.async.wait_group 0;" ::: "memory")

DINL void ldm4(uint32_t* r, uint32_t addr) {
    asm volatile("ldmatrix.sync.aligned.m8n8.x4.shared.b16 {%0,%1,%2,%3}, [%4];"
                 : "=r"(r[0]), "=r"(r[1]), "=r"(r[2]), "=r"(r[3]) : "r"(addr));
}
DINL void mma16816(float* c, const uint32_t* a, uint32_t b0, uint32_t b1) {
    asm volatile(
        "mma.sync.aligned.m16n8k16.row.col.f32.f16.f16.f32 "
        "{%0,%1,%2,%3}, {%4,%5,%6,%7}, {%8,%9}, {%0,%1,%2,%3};"
        : "+f"(c[0]), "+f"(c[1]), "+f"(c[2]), "+f"(c[3])
        : "r"(a[0]), "r"(a[1]), "r"(a[2]), "r"(a[3]), "r"(b0), "r"(b1));
}

// ============================================================================
// Kernel 1 (fused prep): blocks [0, SPLIT_BLOCKS) convert x -> fp16;
// blocks [SPLIT_BLOCKS, +BUILD_BLOCKS) build W_eff = W + A@B -> fp16.
// ============================================================================
__global__ void __launch_bounds__(256) prep_kernel(
    const float* __restrict__ x,
    const float* __restrict__ weight,   // [N,K] row-major
    const float* __restrict__ A,        // [K,RANK]
    const float* __restrict__ B)        // [RANK,N]
{
    __shared__ float As[64][RANK];
    __shared__ float Bs[RANK][256];

    int tid = threadIdx.x;

    if (blockIdx.x < SPLIT_BLOCKS) {
        size_t e = ((size_t)blockIdx.x * 256 + tid) * 8;
        const float4* p = reinterpret_cast<const float4*>(x + e);
        float4 v0 = p[0], v1 = p[1];
        float vv[8] = {v0.x, v0.y, v0.z, v0.w, v1.x, v1.y, v1.z, v1.w};
        __half h[8];
#pragma unroll
        for (int i = 0; i < 8; i++) h[i] = __float2half_rn(vv[i]);
        *reinterpret_cast<uint4*>(g_xh + e) = *reinterpret_cast<uint4*>(h);
        return;
    }

    int bid2 = blockIdx.x - SPLIT_BLOCKS;
    int kblk = bid2 & 63, nblk = bid2 >> 6;
    int d0 = kblk * 64, o0 = nblk * 256;

    reinterpret_cast<float4*>(&As[0][0])[tid] =
        reinterpret_cast<const float4*>(A + (size_t)d0 * RANK)[tid];
#pragma unroll
    for (int r = 0; r < RANK; r++)
        Bs[r][tid] = B[(size_t)r * N_DIM + o0 + tid];
    __syncthreads();

    int o = o0 + tid;
    const float* wrow = weight + (size_t)o * K_DIM + d0;

#pragma unroll 1
    for (int dc = 0; dc < 64; dc += 8) {
        float4 wa = reinterpret_cast<const float4*>(wrow + dc)[0];
        float4 wb = reinterpret_cast<const float4*>(wrow + dc)[1];
        float w[8] = {wa.x, wa.y, wa.z, wa.w, wb.x, wb.y, wb.z, wb.w};
        __half h[8];
#pragma unroll
        for (int i = 0; i < 8; i++) {
            float s = 0.f;
#pragma unroll
            for (int r = 0; r < RANK; r++) s += As[dc + i][r] * Bs[r][tid];
            h[i] = __float2half_rn(w[i] + s);
        }
        *reinterpret_cast<uint4*>(g_wh + (size_t)o * K_DIM + d0 + dc) =
            *reinterpret_cast<uint4*>(h);
    }
}

// ============================================================================
// Kernel 2: GEMM. CTA = 128x128, 128 thr (4 warps, 64x64 tiles), 2 CTAs/SM,
// BK=64, 3-stage cp.async, fp16 mma -> fp32 accum,
// fine-grained [8 MMA | 2 ldm4] interleave, XOR-factored addressing.
// ============================================================================
__global__ void __launch_bounds__(128, 2)
gemm_kernel(const float* __restrict__ bias, float* __restrict__ out)
{
    extern __shared__ __align__(1024) char smem[];
    const uint32_t sbase = smem_u32(smem);

    const int tid  = threadIdx.x;
    const int wid  = tid >> 5;
    const int lane = tid & 31;

    // grouped ordering: groups of (8 m) x (32 n) = 256 CTAs
    const int bid  = blockIdx.x;
    const int grp  = bid >> 8;
    const int mblk = grp * 8 + ((bid >> 5) & 7);
    const int nblk = bid & 31;

    const int m_base = (wid >> 1) * 64;   // 0 or 64
    const int n_base = (wid & 1) * 64;    // 0 or 64

    // ldmatrix lane-relative mapping
    const int r16   = (lane & 7) + ((lane >> 3) & 1) * 8;
    const uint32_t cx = (uint32_t)(lane >> 4) << 4;   // chalf*16 (bit 4)

    // per-thread swizzle bases for ldmatrix: addr = (stage+base) ^ (acol*16)
    uint32_t base_x[4], base_w[4];
#pragma unroll
    for (int mt = 0; mt < 4; mt++) {
        uint32_t row = (uint32_t)(m_base + mt * 16 + r16);
        base_x[mt] = OFF_XH + row * 128 + ((row << 4) & 0x70);
    }
#pragma unroll
    for (int t = 0; t < 4; t++) {
        uint32_t row = (uint32_t)(n_base + t * 16 + r16);
        base_w[t] = OFF_WH + row * 128 + ((row << 4) & 0x70);
    }

    // ---------------- strength-reduced loader state (128 threads) ----------
    const int lrow = tid >> 3;            // 0..15
    const int lcol = (tid & 7) * 8;
    const __half* px = g_xh + (size_t)(mblk * BM + lrow) * K_DIM + lcol;
    const __half* pw = g_wh + (size_t)(nblk * BN + lrow) * K_DIM + lcol;
    const uint32_t sox = OFF_XH + swz((uint32_t)(lrow * 128 + (tid & 7) * 16));
    const uint32_t sow = OFF_WH + swz((uint32_t)(lrow * 128 + (tid & 7) * 16));

    auto load_stage = [&](uint32_t db, const __half* pxk, const __half* pwk,
                          bool valid) {
        if (valid) {
#pragma unroll
            for (int i = 0; i < 8; i++)
                cp16(db + sox + i * 2048, pxk + (size_t)i * 16 * K_DIM);
#pragma unroll
            for (int i = 0; i < 8; i++)
                cp16(db + sow + i * 2048, pwk + (size_t)i * 16 * K_DIM);
        }
        CP_COMMIT();
    };

    float acc[4][8][4];
#pragma unroll
    for (int mt = 0; mt < 4; mt++)
#pragma unroll
        for (int nt = 0; nt < 8; nt++)
#pragma unroll
            for (int q = 0; q < 4; q++) acc[mt][nt][q] = 0.f;

    // prologue: stages 0 and 1 fully loaded
    load_stage(sbase,           px,      pw,      true);
    load_stage(sbase + STAGE_B, px + BK, pw + BK, true);
    px += 2 * BK;  pw += 2 * BK;
    CP_WAIT0();
    __syncthreads();

    uint32_t xa[2][4][4], wf[2][4][4];
#pragma unroll
    for (int mt = 0; mt < 4; mt++) ldm4(xa[0][mt], (sbase + base_x[mt]) ^ cx);
#pragma unroll
    for (int t = 0; t < 4; t++)  ldm4(wf[0][t],  (sbase + base_w[t]) ^ cx);

    int s_cur = 0, s_nxt = 1, s_ld = 2;   // stage indices (mod 3)

#pragma unroll 1
    for (int it = 0; it < NKI; it++) {
        // issue next-next stage load at iter start; a full iteration of MMAs
        // (~2000 cyc >> mem latency) passes before the wait0 below.
        load_stage(sbase + s_ld * STAGE_B, px, pw, it + 2 < NKI);
        px += BK;  pw += BK;

        const uint32_t sb  = sbase + s_cur * STAGE_B;
        const uint32_t sbn = sbase + s_nxt * STAGE_B;

#pragma unroll
        for (int kc = 0; kc < 4; kc++) {
            const int cur = kc & 1, nxt = cur ^ 1;
            // prefetch source: next kc in this stage, or kc0 of next stage
            const uint32_t psb  = (kc < 3) ? sb : sbn;
            const uint32_t pxor = (kc < 3) ? ((uint32_t)((kc + 1) << 5) | cx) : cx;

            // 4 groups of [8 MMA | 2 prefetch ldm4] -> even smem spread,
            // >=8-MMA use distance for every fragment.
#pragma unroll
            for (int g = 0; g < 4; g++) {
                const int mt = g;
#pragma unroll
                for (int nt = 0; nt < 8; nt++)
                    mma16816(acc[mt][nt], xa[cur][mt],
                             wf[cur][nt >> 1][nt & 1], wf[cur][nt >> 1][(nt & 1) + 2]);

                if (g < 2) {
                    ldm4(xa[nxt][2 * g + 0], (psb + base_x[2 * g + 0]) ^ pxor);
                    ldm4(xa[nxt][2 * g + 1], (psb + base_x[2 * g + 1]) ^ pxor);
                } else {
                    ldm4(wf[nxt][2 * (g - 2) + 0], (psb + base_w[2 * (g - 2) + 0]) ^ pxor);
                    ldm4(wf[nxt][2 * (g - 2) + 1], (psb + base_w[2 * (g - 2) + 1]) ^ pxor);
                }
            }
        }

        // wait for the load issued at the start of THIS iter (stage it+2),
        // then barrier before overwriting s_cur next iter.
        CP_WAIT0();
        __syncthreads();

        int t0 = s_cur; s_cur = s_nxt; s_nxt = s_ld; s_ld = t0;
    }

    // ---------------- epilogue: bias add + fp32 store ----------------
    const int gm = mblk * BM + m_base;
    const int gn = nblk * BN + n_base;
#pragma unroll
    for (int nt = 0; nt < 8; nt++) {
        int col = gn + nt * 8 + 2 * (lane & 3);
        float2 bv = *reinterpret_cast<const float2*>(bias + col);
#pragma unroll
        for (int mt = 0; mt < 4; mt++) {
            int row0 = gm + mt * 16 + (lane >> 2);
            float2 v0 = {acc[mt][nt][0] + bv.x, acc[mt][nt][1] + bv.y};
            float2 v1 = {acc[mt][nt][2] + bv.x, acc[mt][nt][3] + bv.y};
            *reinterpret_cast<float2*>(out + (size_t)row0 * N_DIM + col) = v0;
            *reinterpret_cast<float2*>(out + (size_t)(row0 + 8) * N_DIM + col) = v1;
        }
    }
}

// ============================================================================
// Launch
// ============================================================================
extern "C" void kernel_launch(void* const* d_in, const int* in_sizes, int n_in,
                              void* d_out, int out_size)
{
    const float* x      = (const float*)d_in[0];
    const float* A      = (const float*)d_in[1];
    const float* B      = (const float*)d_in[2];
    const float* weight = (const float*)d_in[3];
    const float* bias   = (const float*)d_in[4];
    float* out = (float*)d_out;

    cudaFuncSetAttribute(gemm_kernel,
                         cudaFuncAttributeMaxDynamicSharedMemorySize, SMEM_BYTES);

    prep_kernel<<<SPLIT_BLOCKS + BUILD_BLOCKS, 256>>>(x, weight, A, B);
    gemm_kernel<<<(M_DIM / BM) * (N_DIM / BN), 128, SMEM_BYTES>>>(bias, out);
}